// round 8
// baseline (speedup 1.0000x reference)
#include <cuda_runtime.h>
#include <math.h>
#include <stdint.h>

// GAT layer: B=8, N=1024, IN=256, OUT=256 (H=4 heads x D=64)

#define B_ 8
#define N_ 1024
#define K_ 256
#define O_ 256
#define H_ 4
#define D_ 64
#define CHUNK_ 128
#define ITILE_ 64

__device__ float g_Wh[B_ * N_ * O_];      // [b*N+n][o]  (o = h*64+d), 32 MB
__device__ float g_src[B_ * H_ * N_];
__device__ float g_dst[B_ * H_ * N_];

// ---------------------------------------------------------------------------
// Kernel A: Wh = h @ W^T with fused src/dst epilogue.
// 128x64 tile (o-block = one head), 256 threads, 8x4 micro-tile.
// ---------------------------------------------------------------------------
__global__ void __launch_bounds__(256) gemm_kernel(
    const float* __restrict__ A, const float* __restrict__ Wt,
    const float* __restrict__ avec)
{
    __shared__ float As[16][128];   // [k][m]
    __shared__ float Bs[16][64];    // [k][o]

    int tid = threadIdx.x;
    int tx = tid & 15;
    int ty = tid >> 4;
    int m0 = blockIdx.x * 128;
    int h  = blockIdx.y;
    int o0 = h * 64;

    int arow = tid >> 1;
    int aoff = (tid & 1) * 8;
    int brow = tid & 63;
    int boff = (tid >> 6) * 4;

    float acc[8][4] = {};

    for (int k0 = 0; k0 < K_; k0 += 16) {
        float4 a0 = *reinterpret_cast<const float4*>(A + (size_t)(m0 + arow) * K_ + k0 + aoff);
        float4 a1 = *reinterpret_cast<const float4*>(A + (size_t)(m0 + arow) * K_ + k0 + aoff + 4);
        float4 bv = *reinterpret_cast<const float4*>(Wt + (size_t)(o0 + brow) * K_ + k0 + boff);
        __syncthreads();
        As[aoff + 0][arow] = a0.x; As[aoff + 1][arow] = a0.y;
        As[aoff + 2][arow] = a0.z; As[aoff + 3][arow] = a0.w;
        As[aoff + 4][arow] = a1.x; As[aoff + 5][arow] = a1.y;
        As[aoff + 6][arow] = a1.z; As[aoff + 7][arow] = a1.w;
        Bs[boff + 0][brow] = bv.x; Bs[boff + 1][brow] = bv.y;
        Bs[boff + 2][brow] = bv.z; Bs[boff + 3][brow] = bv.w;
        __syncthreads();

        #pragma unroll
        for (int k = 0; k < 16; ++k) {
            float4 t0 = *reinterpret_cast<const float4*>(&As[k][ty * 8]);
            float4 t1 = *reinterpret_cast<const float4*>(&As[k][ty * 8 + 4]);
            float av[8] = {t0.x, t0.y, t0.z, t0.w, t1.x, t1.y, t1.z, t1.w};
            float bv4[4];
            #pragma unroll
            for (int c = 0; c < 4; ++c) bv4[c] = Bs[k][tx + 16 * c];
            #pragma unroll
            for (int i = 0; i < 8; ++i)
                #pragma unroll
                for (int c = 0; c < 4; ++c)
                    acc[i][c] = fmaf(av[i], bv4[c], acc[i][c]);
        }
    }

    #pragma unroll
    for (int i = 0; i < 8; ++i) {
        float* dst = g_Wh + (size_t)(m0 + ty * 8 + i) * O_ + o0 + tx;
        #pragma unroll
        for (int c = 0; c < 4; ++c) dst[16 * c] = acc[i][c];
    }

    float asv[4], adv[4];
    #pragma unroll
    for (int c = 0; c < 4; ++c) {
        asv[c] = __ldg(avec + h * (2 * D_) + tx + 16 * c);
        adv[c] = __ldg(avec + h * (2 * D_) + D_ + tx + 16 * c);
    }
    int b = m0 >> 10;
    int nbase = (m0 & (N_ - 1)) + ty * 8;
    #pragma unroll
    for (int i = 0; i < 8; ++i) {
        float s = 0.f, t = 0.f;
        #pragma unroll
        for (int c = 0; c < 4; ++c) {
            s = fmaf(acc[i][c], asv[c], s);
            t = fmaf(acc[i][c], adv[c], t);
        }
        #pragma unroll
        for (int off = 8; off; off >>= 1) {
            s += __shfl_xor_sync(0xFFFFFFFFu, s, off);
            t += __shfl_xor_sync(0xFFFFFFFFu, t, off);
        }
        if (tx == 0) {
            g_src[(b * H_ + h) * N_ + nbase + i] = s;
            g_dst[(b * H_ + h) * N_ + nbase + i] = t;
        }
    }
}

// ---------------------------------------------------------------------------
// Kernel B: i-tiled sparse attention. Block = (i-tile of 64, head, batch).
// Warp owns 8 consecutive i-rows; lane owns a d-pair (float2).
// j iterated in 8 chunks of 128; each chunk's Wh rows (32KB) become
// L1-resident -> L2 cold-miss traffic only (128MB total vs 855MB before).
// For each (i, chunk): lane reads 4 mask entries + computes p=exp(leaky(
// src_i+dst_j)) predicated; ballot per sub-slot; iterate set bits with
// shfl-broadcast p + one L1 LDG.64 + 2 FMA. Softmax sum folded into the
// same pass (per-lane partials, warp-reduce at the end). Sorted-j order
// -> deterministic.
// ---------------------------------------------------------------------------
__global__ void __launch_bounds__(256) attn_kernel(
    const void* __restrict__ mask, float* __restrict__ out)
{
    __shared__ int sFlags;

    int tid  = threadIdx.x;
    int lane = tid & 31;
    int warp = tid >> 5;
    int it = blockIdx.x;           // 0..15
    int h  = blockIdx.y;           // 0..3
    int b  = blockIdx.z;           // 0..7

    if (tid == 0) sFlags = 0;
    __syncthreads();

    // mask-kind detection from first 4KB (uint4 per thread, L2 broadcast)
    // uint8 : contains words > 1 (packed 0/1 bytes), never the float pattern
    // int32 : all words in {0,1}
    // float : contains 0x3F800000 words
    {
        uint4 v = reinterpret_cast<const uint4*>(mask)[tid];
        bool isF = (v.x == 0x3F800000u) | (v.y == 0x3F800000u) |
                   (v.z == 0x3F800000u) | (v.w == 0x3F800000u);
        bool isB = ((v.x > 1u) & (v.x != 0x3F800000u)) |
                   ((v.y > 1u) & (v.y != 0x3F800000u)) |
                   ((v.z > 1u) & (v.z != 0x3F800000u)) |
                   ((v.w > 1u) & (v.w != 0x3F800000u));
        unsigned bF = __ballot_sync(0xFFFFFFFFu, isF);
        unsigned bB = __ballot_sync(0xFFFFFFFFu, isB);
        if (lane == 0) {
            int f = (bF ? 1 : 0) | (bB ? 2 : 0);
            if (f) atomicOr(&sFlags, f);
        }
    }
    __syncthreads();
    int flags = sFlags;
    int kind = (flags & 1) ? 2 : ((flags & 2) ? 0 : 1);

    int i0 = it * ITILE_ + warp * 8;          // this warp's 8 rows
    const float* dstv = g_dst + (size_t)(b * H_ + h) * N_;
    float srcv[8];
    #pragma unroll
    for (int r = 0; r < 8; ++r)
        srcv[r] = __ldg(g_src + (size_t)(b * H_ + h) * N_ + i0 + r);

    const float2* whb = reinterpret_cast<const float2*>(
        g_Wh + (size_t)b * N_ * O_ + h * D_) + lane;

    float2 acc[8];
    float  fsum[8];
    #pragma unroll
    for (int r = 0; r < 8; ++r) { acc[r] = make_float2(0.f, 0.f); fsum[r] = 0.f; }

    for (int c = 0; c < N_ / CHUNK_; ++c) {
        int jb = c * CHUNK_ + lane * 4;       // this lane's 4 j's
        float4 dv = *reinterpret_cast<const float4*>(dstv + jb);

        #pragma unroll
        for (int r = 0; r < 8; ++r) {
            size_t mb = ((size_t)b * N_ + (i0 + r)) * N_ + jb;
            bool v0, v1, v2, v3;
            if (kind == 0) {
                uchar4 mv = *reinterpret_cast<const uchar4*>(
                    (const unsigned char*)mask + mb);
                v0 = mv.x; v1 = mv.y; v2 = mv.z; v3 = mv.w;
            } else if (kind == 1) {
                int4 mv = *reinterpret_cast<const int4*>((const int*)mask + mb);
                v0 = mv.x; v1 = mv.y; v2 = mv.z; v3 = mv.w;
            } else {
                float4 mv = *reinterpret_cast<const float4*>((const float*)mask + mb);
                v0 = mv.x != 0.f; v1 = mv.y != 0.f; v2 = mv.z != 0.f; v3 = mv.w != 0.f;
            }
            float s = srcv[r];
            float p0 = 0.f, p1 = 0.f, p2 = 0.f, p3 = 0.f;
            if (v0) { float x = s + dv.x; p0 = __expf(x > 0.f ? x : 0.2f * x); }
            if (v1) { float x = s + dv.y; p1 = __expf(x > 0.f ? x : 0.2f * x); }
            if (v2) { float x = s + dv.z; p2 = __expf(x > 0.f ? x : 0.2f * x); }
            if (v3) { float x = s + dv.w; p3 = __expf(x > 0.f ? x : 0.2f * x); }
            fsum[r] += (p0 + p1) + (p2 + p3);

            unsigned b0 = __ballot_sync(0xFFFFFFFFu, v0);
            unsigned b1 = __ballot_sync(0xFFFFFFFFu, v1);
            unsigned b2 = __ballot_sync(0xFFFFFFFFu, v2);
            unsigned b3 = __ballot_sync(0xFFFFFFFFu, v3);

            while (b0) {
                int l = __ffs(b0) - 1; b0 &= b0 - 1;
                float pb = __shfl_sync(0xFFFFFFFFu, p0, l);
                float2 w = whb[(size_t)(c * CHUNK_ + l * 4 + 0) * 128];
                acc[r].x = fmaf(pb, w.x, acc[r].x);
                acc[r].y = fmaf(pb, w.y, acc[r].y);
            }
            while (b1) {
                int l = __ffs(b1) - 1; b1 &= b1 - 1;
                float pb = __shfl_sync(0xFFFFFFFFu, p1, l);
                float2 w = whb[(size_t)(c * CHUNK_ + l * 4 + 1) * 128];
                acc[r].x = fmaf(pb, w.x, acc[r].x);
                acc[r].y = fmaf(pb, w.y, acc[r].y);
            }
            while (b2) {
                int l = __ffs(b2) - 1; b2 &= b2 - 1;
                float pb = __shfl_sync(0xFFFFFFFFu, p2, l);
                float2 w = whb[(size_t)(c * CHUNK_ + l * 4 + 2) * 128];
                acc[r].x = fmaf(pb, w.x, acc[r].x);
                acc[r].y = fmaf(pb, w.y, acc[r].y);
            }
            while (b3) {
                int l = __ffs(b3) - 1; b3 &= b3 - 1;
                float pb = __shfl_sync(0xFFFFFFFFu, p3, l);
                float2 w = whb[(size_t)(c * CHUNK_ + l * 4 + 3) * 128];
                acc[r].x = fmaf(pb, w.x, acc[r].x);
                acc[r].y = fmaf(pb, w.y, acc[r].y);
            }
        }
    }

    // epilogue: reduce sums, scale, coalesced float2 stores
    #pragma unroll
    for (int r = 0; r < 8; ++r) {
        float s = fsum[r];
        #pragma unroll
        for (int off = 16; off; off >>= 1)
            s += __shfl_xor_sync(0xFFFFFFFFu, s, off);
        float inv = (s > 0.f) ? (1.0f / s) : 0.f;
        float2 o = make_float2(acc[r].x * inv, acc[r].y * inv);
        *reinterpret_cast<float2*>(
            out + ((size_t)(b * N_ + i0 + r)) * O_ + h * D_ + lane * 2) = o;
    }
}

// ---------------------------------------------------------------------------
extern "C" void kernel_launch(void* const* d_in, const int* in_sizes, int n_in,
                              void* d_out, int out_size) {
    const float* h = nullptr;
    const float* W = nullptr;
    const float* a = nullptr;
    const void*  mask = nullptr;

    for (int idx = 0; idx < n_in; ++idx) {
        switch (in_sizes[idx]) {
            case B_ * N_ * K_: h    = (const float*)d_in[idx]; break;
            case K_ * O_:      W    = (const float*)d_in[idx]; break;
            case H_ * 2 * D_:  a    = (const float*)d_in[idx]; break;
            case B_ * N_ * N_: mask = d_in[idx];               break;
        }
    }
    if (!h)    h    = (const float*)d_in[0];
    if (!W)    W    = (const float*)d_in[1];
    if (!a)    a    = (const float*)d_in[2];
    if (!mask) mask = d_in[3];

    gemm_kernel<<<dim3((B_ * N_) / 128, H_), 256>>>(h, W, a);
    attn_kernel<<<dim3(N_ / ITILE_, H_, B_), 256>>>(mask, (float*)d_out);
}

// round 9
// speedup vs baseline: 1.6955x; 1.6955x over previous
#include <cuda_runtime.h>
#include <math.h>
#include <stdint.h>

// GAT layer: B=8, N=1024, IN=256, OUT=256 (H=4 heads x D=64)

#define B_ 8
#define N_ 1024
#define K_ 256
#define O_ 256
#define H_ 4
#define D_ 64

__device__ float g_Wh[B_ * N_ * O_];      // [b*N+n][o]  (o = h*64+d), 32 MB
__device__ float g_src[B_ * H_ * N_];
__device__ float g_dst[B_ * H_ * N_];

// ---------------------------------------------------------------------------
// Kernel A: Wh = h @ W^T with fused src/dst epilogue.
// 128x64 tile (o-block = one head), 256 threads, 8x4 micro-tile.
// ---------------------------------------------------------------------------
__global__ void __launch_bounds__(256) gemm_kernel(
    const float* __restrict__ A, const float* __restrict__ Wt,
    const float* __restrict__ avec)
{
    __shared__ float As[16][128];   // [k][m]
    __shared__ float Bs[16][64];    // [k][o]

    int tid = threadIdx.x;
    int tx = tid & 15;
    int ty = tid >> 4;
    int m0 = blockIdx.x * 128;
    int h  = blockIdx.y;
    int o0 = h * 64;

    int arow = tid >> 1;
    int aoff = (tid & 1) * 8;
    int brow = tid & 63;
    int boff = (tid >> 6) * 4;

    float acc[8][4] = {};

    for (int k0 = 0; k0 < K_; k0 += 16) {
        float4 a0 = *reinterpret_cast<const float4*>(A + (size_t)(m0 + arow) * K_ + k0 + aoff);
        float4 a1 = *reinterpret_cast<const float4*>(A + (size_t)(m0 + arow) * K_ + k0 + aoff + 4);
        float4 bv = *reinterpret_cast<const float4*>(Wt + (size_t)(o0 + brow) * K_ + k0 + boff);
        __syncthreads();
        As[aoff + 0][arow] = a0.x; As[aoff + 1][arow] = a0.y;
        As[aoff + 2][arow] = a0.z; As[aoff + 3][arow] = a0.w;
        As[aoff + 4][arow] = a1.x; As[aoff + 5][arow] = a1.y;
        As[aoff + 6][arow] = a1.z; As[aoff + 7][arow] = a1.w;
        Bs[boff + 0][brow] = bv.x; Bs[boff + 1][brow] = bv.y;
        Bs[boff + 2][brow] = bv.z; Bs[boff + 3][brow] = bv.w;
        __syncthreads();

        #pragma unroll
        for (int k = 0; k < 16; ++k) {
            float4 t0 = *reinterpret_cast<const float4*>(&As[k][ty * 8]);
            float4 t1 = *reinterpret_cast<const float4*>(&As[k][ty * 8 + 4]);
            float av[8] = {t0.x, t0.y, t0.z, t0.w, t1.x, t1.y, t1.z, t1.w};
            float bv4[4];
            #pragma unroll
            for (int c = 0; c < 4; ++c) bv4[c] = Bs[k][tx + 16 * c];
            #pragma unroll
            for (int i = 0; i < 8; ++i)
                #pragma unroll
                for (int c = 0; c < 4; ++c)
                    acc[i][c] = fmaf(av[i], bv4[c], acc[i][c]);
        }
    }

    #pragma unroll
    for (int i = 0; i < 8; ++i) {
        float* dst = g_Wh + (size_t)(m0 + ty * 8 + i) * O_ + o0 + tx;
        #pragma unroll
        for (int c = 0; c < 4; ++c) dst[16 * c] = acc[i][c];
    }

    float asv[4], adv[4];
    #pragma unroll
    for (int c = 0; c < 4; ++c) {
        asv[c] = __ldg(avec + h * (2 * D_) + tx + 16 * c);
        adv[c] = __ldg(avec + h * (2 * D_) + D_ + tx + 16 * c);
    }
    int b = m0 >> 10;
    int nbase = (m0 & (N_ - 1)) + ty * 8;
    #pragma unroll
    for (int i = 0; i < 8; ++i) {
        float s = 0.f, t = 0.f;
        #pragma unroll
        for (int c = 0; c < 4; ++c) {
            s = fmaf(acc[i][c], asv[c], s);
            t = fmaf(acc[i][c], adv[c], t);
        }
        #pragma unroll
        for (int off = 8; off; off >>= 1) {
            s += __shfl_xor_sync(0xFFFFFFFFu, s, off);
            t += __shfl_xor_sync(0xFFFFFFFFu, t, off);
        }
        if (tx == 0) {
            g_src[(b * H_ + h) * N_ + nbase + i] = s;
            g_dst[(b * H_ + h) * N_ + nbase + i] = t;
        }
    }
}

// ---------------------------------------------------------------------------
// Kernel B: attention. One block per (b,i), 256 threads.
//   pre:     mask-kind classification from first 4KB of mask (L2 broadcast)
//   phase 0: deterministic scan-based compaction into sh_idx (sorted j),
//            padded to a multiple of 8 with sentinels
//   phase 1: per-head (64-lane group): e -> p=expf(e), packed (p,j) float2,
//            sum (no max subtraction: |e| <~ 7, exp safe; softmax identical)
//   phase 2: warp = (head, k-parity): each warp gathers half the list with
//            FOUR independent float2 Wh loads in flight (k,k+2,k+4,k+6;
//            step 8) -> 2x the gather MLP of round 7; combine in shared.
// ---------------------------------------------------------------------------
__global__ void __launch_bounds__(256) attn_kernel(
    const void* __restrict__ mask, float* __restrict__ out)
{
    __shared__ unsigned short sh_idx[N_ + 8];  // 2KB
    __shared__ float2 sh_pj[H_][N_ + 8];       // 32KB+: (p, j-bits)
    __shared__ int   sWc[32];
    __shared__ int   sOff[32];
    __shared__ int   sCnt;
    __shared__ int   sFlags;
    __shared__ float sred[H_][2];
    __shared__ float sacc[8][64];              // 2KB

    int tid = threadIdx.x;
    int bid = blockIdx.x;                      // b*N + i
    int i = bid & (N_ - 1);
    int b = bid >> 10;
    int lane = tid & 31;
    int warp = tid >> 5;

    if (tid == 0) sFlags = 0;
    __syncthreads();

    // mask-kind detection from first 4KB (uint4 per thread, L2 broadcast)
    {
        uint4 v = reinterpret_cast<const uint4*>(mask)[tid];
        bool isF = (v.x == 0x3F800000u) | (v.y == 0x3F800000u) |
                   (v.z == 0x3F800000u) | (v.w == 0x3F800000u);
        bool isB = ((v.x > 1u) & (v.x != 0x3F800000u)) |
                   ((v.y > 1u) & (v.y != 0x3F800000u)) |
                   ((v.z > 1u) & (v.z != 0x3F800000u)) |
                   ((v.w > 1u) & (v.w != 0x3F800000u));
        unsigned bF = __ballot_sync(0xFFFFFFFFu, isF);
        unsigned bB = __ballot_sync(0xFFFFFFFFu, isB);
        if (lane == 0) {
            int f = (bF ? 1 : 0) | (bB ? 2 : 0);
            if (f) atomicOr(&sFlags, f);
        }
    }
    __syncthreads();
    int flags = sFlags;
    int kind = (flags & 1) ? 2 : ((flags & 2) ? 0 : 1);

    size_t mbase = ((size_t)b * N_ + i) * N_;

    // phase 0a: ballots for all 4 rounds
    unsigned bal[4];
    #pragma unroll
    for (int r = 0; r < 4; ++r) {
        int j = r * 256 + warp * 32 + lane;
        bool valid;
        if (kind == 0)      valid = ((const unsigned char*)mask)[mbase + j] != 0;
        else if (kind == 1) valid = ((const int*)mask)[mbase + j] != 0;
        else                valid = ((const float*)mask)[mbase + j] != 0.0f;
        bal[r] = __ballot_sync(0xFFFFFFFFu, valid);
    }
    if (lane == 0) {
        sWc[0 * 8 + warp] = __popc(bal[0]);
        sWc[1 * 8 + warp] = __popc(bal[1]);
        sWc[2 * 8 + warp] = __popc(bal[2]);
        sWc[3 * 8 + warp] = __popc(bal[3]);
    }
    __syncthreads();

    // phase 0b: exclusive scan over the 32 counts (warp 0)
    if (warp == 0) {
        int c = sWc[lane];
        int x = c;
        #pragma unroll
        for (int off = 1; off < 32; off <<= 1) {
            int y = __shfl_up_sync(0xFFFFFFFFu, x, off);
            if (lane >= off) x += y;
        }
        sOff[lane] = x - c;
        if (lane == 31) sCnt = x;
    }
    __syncthreads();
    int cnt = sCnt;
    int pad = (cnt + 7) & ~7;

    // phase 0c: indexed writes (sorted j order) + sentinel padding
    #pragma unroll
    for (int r = 0; r < 4; ++r) {
        if ((bal[r] >> lane) & 1u) {
            int pos = sOff[r * 8 + warp] + __popc(bal[r] & ((1u << lane) - 1u));
            sh_idx[pos] = (unsigned short)(r * 256 + warp * 32 + lane);
        }
    }
    if (tid < pad - cnt) sh_idx[cnt + tid] = 0;
    __syncthreads();

    int h   = tid >> 6;
    int l64 = tid & 63;
    int wig = (tid >> 5) & 1;

    const float* dstv = g_dst + (size_t)(b * H_ + h) * N_;
    float srci = __ldg(g_src + (size_t)(b * H_ + h) * N_ + i);

    // phase 1: e -> p, packed (p,j), sum (sentinels get p=0)
    float lsum = 0.f;
    for (int k = l64; k < pad; k += 64) {
        unsigned j = sh_idx[k];
        float p = 0.f;
        if (k < cnt) {
            float x = srci + dstv[j];
            float e = x > 0.f ? x : 0.2f * x;
            p = __expf(e);
        }
        sh_pj[h][k] = make_float2(p, __uint_as_float(j));
        lsum += p;
    }
    #pragma unroll
    for (int off = 16; off; off >>= 1)
        lsum += __shfl_xor_sync(0xFFFFFFFFu, lsum, off);
    if (lane == 0) sred[h][wig] = lsum;
    __syncthreads();

    // phase 2: warp = (head, k-parity). Lane owns a d-pair (float2).
    // Four independent gathers in flight per loop body.
    {
        int hh   = warp >> 1;
        int half = warp & 1;
        const float2* whb = reinterpret_cast<const float2*>(
            g_Wh + (size_t)b * N_ * O_ + hh * D_) + lane;
        const float2* pj = sh_pj[hh];
        float ax = 0.f, ay = 0.f;
        for (int k = half; k < pad; k += 8) {
            float2 q0 = pj[k];
            float2 q1 = pj[k + 2];
            float2 q2 = pj[k + 4];
            float2 q3 = pj[k + 6];
            float2 w0 = whb[(size_t)__float_as_uint(q0.y) * 128];
            float2 w1 = whb[(size_t)__float_as_uint(q1.y) * 128];
            float2 w2 = whb[(size_t)__float_as_uint(q2.y) * 128];
            float2 w3 = whb[(size_t)__float_as_uint(q3.y) * 128];
            ax = fmaf(q0.x, w0.x, ax);
            ay = fmaf(q0.x, w0.y, ay);
            ax = fmaf(q1.x, w1.x, ax);
            ay = fmaf(q1.x, w1.y, ay);
            ax = fmaf(q2.x, w2.x, ax);
            ay = fmaf(q2.x, w2.y, ay);
            ax = fmaf(q3.x, w3.x, ax);
            ay = fmaf(q3.x, w3.y, ay);
        }
        sacc[warp][lane * 2]     = ax;
        sacc[warp][lane * 2 + 1] = ay;
    }
    __syncthreads();

    // combine halves + scale + coalesced store
    {
        int hh = tid >> 6;
        int d  = tid & 63;
        float ssum = sred[hh][0] + sred[hh][1];
        float inv = (ssum > 0.f) ? (1.0f / ssum) : 0.f;
        float v = (sacc[2 * hh][d] + sacc[2 * hh + 1][d]) * inv;
        out[(size_t)bid * O_ + hh * D_ + d] = v;
    }
}

// ---------------------------------------------------------------------------
extern "C" void kernel_launch(void* const* d_in, const int* in_sizes, int n_in,
                              void* d_out, int out_size) {
    const float* h = nullptr;
    const float* W = nullptr;
    const float* a = nullptr;
    const void*  mask = nullptr;

    for (int idx = 0; idx < n_in; ++idx) {
        switch (in_sizes[idx]) {
            case B_ * N_ * K_: h    = (const float*)d_in[idx]; break;
            case K_ * O_:      W    = (const float*)d_in[idx]; break;
            case H_ * 2 * D_:  a    = (const float*)d_in[idx]; break;
            case B_ * N_ * N_: mask = d_in[idx];               break;
        }
    }
    if (!h)    h    = (const float*)d_in[0];
    if (!W)    W    = (const float*)d_in[1];
    if (!a)    a    = (const float*)d_in[2];
    if (!mask) mask = d_in[3];

    gemm_kernel<<<dim3((B_ * N_) / 128, H_), 256>>>(h, W, a);
    attn_kernel<<<B_ * N_, 256>>>(mask, (float*)d_out);
}

// round 10
// speedup vs baseline: 1.7001x; 1.0027x over previous
#include <cuda_runtime.h>
#include <math.h>
#include <stdint.h>

// GAT layer: B=8, N=1024, IN=256, OUT=256 (H=4 heads x D=64)

#define B_ 8
#define N_ 1024
#define K_ 256
#define O_ 256
#define H_ 4
#define D_ 64

__device__ float g_Wh[B_ * N_ * O_];      // [b*N+n][o]  (o = h*64+d), 32 MB
__device__ float g_src[B_ * H_ * N_];
__device__ float g_dst[B_ * H_ * N_];

// ---------------------------------------------------------------------------
// Kernel A: Wh = h @ W^T with fused src/dst epilogue.
// 128x64 tile (o-block = one head), 256 threads, 8x4 micro-tile.
// ---------------------------------------------------------------------------
__global__ void __launch_bounds__(256) gemm_kernel(
    const float* __restrict__ A, const float* __restrict__ Wt,
    const float* __restrict__ avec)
{
    __shared__ float As[16][128];   // [k][m]
    __shared__ float Bs[16][64];    // [k][o]

    int tid = threadIdx.x;
    int tx = tid & 15;
    int ty = tid >> 4;
    int m0 = blockIdx.x * 128;
    int h  = blockIdx.y;
    int o0 = h * 64;

    int arow = tid >> 1;
    int aoff = (tid & 1) * 8;
    int brow = tid & 63;
    int boff = (tid >> 6) * 4;

    float acc[8][4] = {};

    for (int k0 = 0; k0 < K_; k0 += 16) {
        float4 a0 = *reinterpret_cast<const float4*>(A + (size_t)(m0 + arow) * K_ + k0 + aoff);
        float4 a1 = *reinterpret_cast<const float4*>(A + (size_t)(m0 + arow) * K_ + k0 + aoff + 4);
        float4 bv = *reinterpret_cast<const float4*>(Wt + (size_t)(o0 + brow) * K_ + k0 + boff);
        __syncthreads();
        As[aoff + 0][arow] = a0.x; As[aoff + 1][arow] = a0.y;
        As[aoff + 2][arow] = a0.z; As[aoff + 3][arow] = a0.w;
        As[aoff + 4][arow] = a1.x; As[aoff + 5][arow] = a1.y;
        As[aoff + 6][arow] = a1.z; As[aoff + 7][arow] = a1.w;
        Bs[boff + 0][brow] = bv.x; Bs[boff + 1][brow] = bv.y;
        Bs[boff + 2][brow] = bv.z; Bs[boff + 3][brow] = bv.w;
        __syncthreads();

        #pragma unroll
        for (int k = 0; k < 16; ++k) {
            float4 t0 = *reinterpret_cast<const float4*>(&As[k][ty * 8]);
            float4 t1 = *reinterpret_cast<const float4*>(&As[k][ty * 8 + 4]);
            float av[8] = {t0.x, t0.y, t0.z, t0.w, t1.x, t1.y, t1.z, t1.w};
            float bv4[4];
            #pragma unroll
            for (int c = 0; c < 4; ++c) bv4[c] = Bs[k][tx + 16 * c];
            #pragma unroll
            for (int i = 0; i < 8; ++i)
                #pragma unroll
                for (int c = 0; c < 4; ++c)
                    acc[i][c] = fmaf(av[i], bv4[c], acc[i][c]);
        }
    }

    #pragma unroll
    for (int i = 0; i < 8; ++i) {
        float* dst = g_Wh + (size_t)(m0 + ty * 8 + i) * O_ + o0 + tx;
        #pragma unroll
        for (int c = 0; c < 4; ++c) dst[16 * c] = acc[i][c];
    }

    float asv[4], adv[4];
    #pragma unroll
    for (int c = 0; c < 4; ++c) {
        asv[c] = __ldg(avec + h * (2 * D_) + tx + 16 * c);
        adv[c] = __ldg(avec + h * (2 * D_) + D_ + tx + 16 * c);
    }
    int b = m0 >> 10;
    int nbase = (m0 & (N_ - 1)) + ty * 8;
    #pragma unroll
    for (int i = 0; i < 8; ++i) {
        float s = 0.f, t = 0.f;
        #pragma unroll
        for (int c = 0; c < 4; ++c) {
            s = fmaf(acc[i][c], asv[c], s);
            t = fmaf(acc[i][c], adv[c], t);
        }
        #pragma unroll
        for (int off = 8; off; off >>= 1) {
            s += __shfl_xor_sync(0xFFFFFFFFu, s, off);
            t += __shfl_xor_sync(0xFFFFFFFFu, t, off);
        }
        if (tx == 0) {
            g_src[(b * H_ + h) * N_ + nbase + i] = s;
            g_dst[(b * H_ + h) * N_ + nbase + i] = t;
        }
    }
}

// ---------------------------------------------------------------------------
// Kernel B: attention. One block per (b,i), 256 threads.
//   pre:     mask-kind classification from first 4KB of mask (L2 broadcast)
//   phase 0: deterministic scan-based compaction into sh_idx (sorted j),
//            padded to a multiple of 8 with sentinels
//   phase 1: per-head (64-lane group): e -> p=expf(e), packed (p,j) float2,
//            sum (no max subtraction: |e| <~ 7, exp safe; softmax identical)
//   phase 2: warp = (head, contiguous half-segment). Software-pipelined:
//            next iteration's (p,j) quad prefetched (2x LDS.128) while the
//            current four gathers + FMAs retire -> LDS latency hidden,
//            gather addresses always ready.
// ---------------------------------------------------------------------------
__global__ void __launch_bounds__(256) attn_kernel(
    const void* __restrict__ mask, float* __restrict__ out)
{
    __shared__ unsigned short sh_idx[N_ + 8];              // 2KB
    __shared__ __align__(16) float2 sh_pj[H_][N_ + 8];     // 32KB+: (p, j-bits)
    __shared__ int   sWc[32];
    __shared__ int   sOff[32];
    __shared__ int   sCnt;
    __shared__ int   sFlags;
    __shared__ float sred[H_][2];
    __shared__ float sacc[8][64];                          // 2KB

    int tid = threadIdx.x;
    int bid = blockIdx.x;                      // b*N + i
    int i = bid & (N_ - 1);
    int b = bid >> 10;
    int lane = tid & 31;
    int warp = tid >> 5;

    if (tid == 0) sFlags = 0;
    __syncthreads();

    // mask-kind detection from first 4KB (uint4 per thread, L2 broadcast)
    {
        uint4 v = reinterpret_cast<const uint4*>(mask)[tid];
        bool isF = (v.x == 0x3F800000u) | (v.y == 0x3F800000u) |
                   (v.z == 0x3F800000u) | (v.w == 0x3F800000u);
        bool isB = ((v.x > 1u) & (v.x != 0x3F800000u)) |
                   ((v.y > 1u) & (v.y != 0x3F800000u)) |
                   ((v.z > 1u) & (v.z != 0x3F800000u)) |
                   ((v.w > 1u) & (v.w != 0x3F800000u));
        unsigned bF = __ballot_sync(0xFFFFFFFFu, isF);
        unsigned bB = __ballot_sync(0xFFFFFFFFu, isB);
        if (lane == 0) {
            int f = (bF ? 1 : 0) | (bB ? 2 : 0);
            if (f) atomicOr(&sFlags, f);
        }
    }
    __syncthreads();
    int flags = sFlags;
    int kind = (flags & 1) ? 2 : ((flags & 2) ? 0 : 1);

    size_t mbase = ((size_t)b * N_ + i) * N_;

    // phase 0a: load all 4 rounds' mask values first (batched), then ballots
    bool vv[4];
    #pragma unroll
    for (int r = 0; r < 4; ++r) {
        int j = r * 256 + warp * 32 + lane;
        if (kind == 0)      vv[r] = ((const unsigned char*)mask)[mbase + j] != 0;
        else if (kind == 1) vv[r] = ((const int*)mask)[mbase + j] != 0;
        else                vv[r] = ((const float*)mask)[mbase + j] != 0.0f;
    }
    unsigned bal[4];
    #pragma unroll
    for (int r = 0; r < 4; ++r)
        bal[r] = __ballot_sync(0xFFFFFFFFu, vv[r]);
    if (lane == 0) {
        sWc[0 * 8 + warp] = __popc(bal[0]);
        sWc[1 * 8 + warp] = __popc(bal[1]);
        sWc[2 * 8 + warp] = __popc(bal[2]);
        sWc[3 * 8 + warp] = __popc(bal[3]);
    }
    __syncthreads();

    // phase 0b: exclusive scan over the 32 counts (warp 0)
    if (warp == 0) {
        int c = sWc[lane];
        int x = c;
        #pragma unroll
        for (int off = 1; off < 32; off <<= 1) {
            int y = __shfl_up_sync(0xFFFFFFFFu, x, off);
            if (lane >= off) x += y;
        }
        sOff[lane] = x - c;
        if (lane == 31) sCnt = x;
    }
    __syncthreads();
    int cnt = sCnt;
    int pad = (cnt + 7) & ~7;

    // phase 0c: indexed writes (sorted j order) + sentinel padding
    #pragma unroll
    for (int r = 0; r < 4; ++r) {
        if ((bal[r] >> lane) & 1u) {
            int pos = sOff[r * 8 + warp] + __popc(bal[r] & ((1u << lane) - 1u));
            sh_idx[pos] = (unsigned short)(r * 256 + warp * 32 + lane);
        }
    }
    if (tid < pad - cnt) sh_idx[cnt + tid] = 0;
    __syncthreads();

    int h   = tid >> 6;
    int l64 = tid & 63;
    int wig = (tid >> 5) & 1;

    const float* dstv = g_dst + (size_t)(b * H_ + h) * N_;
    float srci = __ldg(g_src + (size_t)(b * H_ + h) * N_ + i);

    // phase 1: e -> p, packed (p,j), sum (sentinels get p=0)
    float lsum = 0.f;
    for (int k = l64; k < pad; k += 64) {
        unsigned j = sh_idx[k];
        float p = 0.f;
        if (k < cnt) {
            float x = srci + dstv[j];
            float e = x > 0.f ? x : 0.2f * x;
            p = __expf(e);
        }
        sh_pj[h][k] = make_float2(p, __uint_as_float(j));
        lsum += p;
    }
    #pragma unroll
    for (int off = 16; off; off >>= 1)
        lsum += __shfl_xor_sync(0xFFFFFFFFu, lsum, off);
    if (lane == 0) sred[h][wig] = lsum;
    __syncthreads();

    // phase 2: warp = (head, contiguous half-segment). Lane owns a d-pair.
    // Software pipeline: prefetch next (p,j) quad before current FMAs.
    {
        int hh   = warp >> 1;
        int half = warp & 1;
        int seg  = pad >> 1;                   // multiple of 4
        int idx  = (half * seg) >> 1;          // float4 pair-index
        int end  = idx + (seg >> 1);
        const float2* whb = reinterpret_cast<const float2*>(
            g_Wh + (size_t)b * N_ * O_ + hh * D_) + lane;
        const float4* pj4 = reinterpret_cast<const float4*>(sh_pj[hh]);
        float ax = 0.f, ay = 0.f;
        if (idx < end) {
            float4 qa = pj4[idx];              // pairs (k0,k1): (p0,j0,p1,j1)
            float4 qb = pj4[idx + 1];          // pairs (k2,k3)
            for (;;) {
                float2 w0 = whb[(size_t)__float_as_uint(qa.y) * 128];
                float2 w1 = whb[(size_t)__float_as_uint(qa.w) * 128];
                float2 w2 = whb[(size_t)__float_as_uint(qb.y) * 128];
                float2 w3 = whb[(size_t)__float_as_uint(qb.w) * 128];
                float p0 = qa.x, p1 = qa.z, p2 = qb.x, p3 = qb.z;
                idx += 2;
                bool more = idx < end;
                float4 na, nb;
                if (more) { na = pj4[idx]; nb = pj4[idx + 1]; }
                ax = fmaf(p0, w0.x, ax);
                ay = fmaf(p0, w0.y, ay);
                ax = fmaf(p1, w1.x, ax);
                ay = fmaf(p1, w1.y, ay);
                ax = fmaf(p2, w2.x, ax);
                ay = fmaf(p2, w2.y, ay);
                ax = fmaf(p3, w3.x, ax);
                ay = fmaf(p3, w3.y, ay);
                if (!more) break;
                qa = na; qb = nb;
            }
        }
        sacc[warp][lane * 2]     = ax;
        sacc[warp][lane * 2 + 1] = ay;
    }
    __syncthreads();

    // combine halves + scale + coalesced store
    {
        int hh = tid >> 6;
        int d  = tid & 63;
        float ssum = sred[hh][0] + sred[hh][1];
        float inv = (ssum > 0.f) ? (1.0f / ssum) : 0.f;
        float v = (sacc[2 * hh][d] + sacc[2 * hh + 1][d]) * inv;
        out[(size_t)bid * O_ + hh * D_ + d] = v;
    }
}

// ---------------------------------------------------------------------------
extern "C" void kernel_launch(void* const* d_in, const int* in_sizes, int n_in,
                              void* d_out, int out_size) {
    const float* h = nullptr;
    const float* W = nullptr;
    const float* a = nullptr;
    const void*  mask = nullptr;

    for (int idx = 0; idx < n_in; ++idx) {
        switch (in_sizes[idx]) {
            case B_ * N_ * K_: h    = (const float*)d_in[idx]; break;
            case K_ * O_:      W    = (const float*)d_in[idx]; break;
            case H_ * 2 * D_:  a    = (const float*)d_in[idx]; break;
            case B_ * N_ * N_: mask = d_in[idx];               break;
        }
    }
    if (!h)    h    = (const float*)d_in[0];
    if (!W)    W    = (const float*)d_in[1];
    if (!a)    a    = (const float*)d_in[2];
    if (!mask) mask = d_in[3];

    gemm_kernel<<<dim3((B_ * N_) / 128, H_), 256>>>(h, W, a);
    attn_kernel<<<B_ * N_, 256>>>(mask, (float*)d_out);
}

// round 11
// speedup vs baseline: 1.8375x; 1.0808x over previous
#include <cuda_runtime.h>
#include <math.h>
#include <stdint.h>

// GAT layer: B=8, N=1024, IN=256, OUT=256 (H=4 heads x D=64)

#define B_ 8
#define N_ 1024
#define K_ 256
#define O_ 256
#define H_ 4
#define D_ 64

__device__ float g_Wh[B_ * N_ * O_];      // [b*N+n][o]  (o = h*64+d), 32 MB
__device__ float g_src[B_ * H_ * N_];
__device__ float g_dst[B_ * H_ * N_];

// ---------------------------------------------------------------------------
// Kernel A: Wh = h @ W^T with fused src/dst epilogue.
// 128x64 tile (o-block = one head), 256 threads, 8x4 micro-tile.
// ---------------------------------------------------------------------------
__global__ void __launch_bounds__(256) gemm_kernel(
    const float* __restrict__ A, const float* __restrict__ Wt,
    const float* __restrict__ avec)
{
    __shared__ float As[16][128];   // [k][m]
    __shared__ float Bs[16][64];    // [k][o]

    int tid = threadIdx.x;
    int tx = tid & 15;
    int ty = tid >> 4;
    int m0 = blockIdx.x * 128;
    int h  = blockIdx.y;
    int o0 = h * 64;

    int arow = tid >> 1;
    int aoff = (tid & 1) * 8;
    int brow = tid & 63;
    int boff = (tid >> 6) * 4;

    float acc[8][4] = {};

    for (int k0 = 0; k0 < K_; k0 += 16) {
        float4 a0 = *reinterpret_cast<const float4*>(A + (size_t)(m0 + arow) * K_ + k0 + aoff);
        float4 a1 = *reinterpret_cast<const float4*>(A + (size_t)(m0 + arow) * K_ + k0 + aoff + 4);
        float4 bv = *reinterpret_cast<const float4*>(Wt + (size_t)(o0 + brow) * K_ + k0 + boff);
        __syncthreads();
        As[aoff + 0][arow] = a0.x; As[aoff + 1][arow] = a0.y;
        As[aoff + 2][arow] = a0.z; As[aoff + 3][arow] = a0.w;
        As[aoff + 4][arow] = a1.x; As[aoff + 5][arow] = a1.y;
        As[aoff + 6][arow] = a1.z; As[aoff + 7][arow] = a1.w;
        Bs[boff + 0][brow] = bv.x; Bs[boff + 1][brow] = bv.y;
        Bs[boff + 2][brow] = bv.z; Bs[boff + 3][brow] = bv.w;
        __syncthreads();

        #pragma unroll
        for (int k = 0; k < 16; ++k) {
            float4 t0 = *reinterpret_cast<const float4*>(&As[k][ty * 8]);
            float4 t1 = *reinterpret_cast<const float4*>(&As[k][ty * 8 + 4]);
            float av[8] = {t0.x, t0.y, t0.z, t0.w, t1.x, t1.y, t1.z, t1.w};
            float bv4[4];
            #pragma unroll
            for (int c = 0; c < 4; ++c) bv4[c] = Bs[k][tx + 16 * c];
            #pragma unroll
            for (int i = 0; i < 8; ++i)
                #pragma unroll
                for (int c = 0; c < 4; ++c)
                    acc[i][c] = fmaf(av[i], bv4[c], acc[i][c]);
        }
    }

    #pragma unroll
    for (int i = 0; i < 8; ++i) {
        float* dst = g_Wh + (size_t)(m0 + ty * 8 + i) * O_ + o0 + tx;
        #pragma unroll
        for (int c = 0; c < 4; ++c) dst[16 * c] = acc[i][c];
    }

    float asv[4], adv[4];
    #pragma unroll
    for (int c = 0; c < 4; ++c) {
        asv[c] = __ldg(avec + h * (2 * D_) + tx + 16 * c);
        adv[c] = __ldg(avec + h * (2 * D_) + D_ + tx + 16 * c);
    }
    int b = m0 >> 10;
    int nbase = (m0 & (N_ - 1)) + ty * 8;
    #pragma unroll
    for (int i = 0; i < 8; ++i) {
        float s = 0.f, t = 0.f;
        #pragma unroll
        for (int c = 0; c < 4; ++c) {
            s = fmaf(acc[i][c], asv[c], s);
            t = fmaf(acc[i][c], adv[c], t);
        }
        #pragma unroll
        for (int off = 8; off; off >>= 1) {
            s += __shfl_xor_sync(0xFFFFFFFFu, s, off);
            t += __shfl_xor_sync(0xFFFFFFFFu, t, off);
        }
        if (tx == 0) {
            g_src[(b * H_ + h) * N_ + nbase + i] = s;
            g_dst[(b * H_ + h) * N_ + nbase + i] = t;
        }
    }
}

// ---------------------------------------------------------------------------
// Kernel B: attention. One block per (b,i), 256 threads, 8 blocks/SM.
//   pre:     mask-kind classification from first 4KB of mask (L2 broadcast)
//   phase 0: deterministic scan-based compaction into sh_idx (sorted j),
//            padded to a multiple of 8 with sentinels
//   phase 1: per-head (64-lane group): e -> p=expf(e); p and j PACKED into
//            one uint32 (j in the low 10 mantissa bits of p; quantized p
//            used consistently in sum and FMAs -> rel err ~1e-4, 20x under
//            tolerance). Halves the smem footprint (33KB -> 16.5KB) so 8
//            blocks/SM fit -> ~100% occupancy -> +40% outstanding gathers.
//   phase 2: warp = (head, k-parity): one LDS.128 broadcasts FOUR packed
//            neighbors; 4 independent float2 gathers + 8 FMA per iter.
// ---------------------------------------------------------------------------
__global__ void __launch_bounds__(256, 8) attn_kernel(
    const void* __restrict__ mask, float* __restrict__ out)
{
    __shared__ unsigned short sh_idx[N_ + 8];              // 2KB
    __shared__ __align__(16) unsigned sh_pk[H_][N_ + 8];   // 16.5KB packed (p|j)
    __shared__ int   sWc[32];
    __shared__ int   sOff[32];
    __shared__ int   sCnt;
    __shared__ int   sFlags;
    __shared__ float sred[H_][2];
    __shared__ float sacc[8][64];                          // 2KB

    int tid = threadIdx.x;
    int bid = blockIdx.x;                      // b*N + i
    int i = bid & (N_ - 1);
    int b = bid >> 10;
    int lane = tid & 31;
    int warp = tid >> 5;

    if (tid == 0) sFlags = 0;
    __syncthreads();

    // mask-kind detection from first 4KB (uint4 per thread, L2 broadcast)
    {
        uint4 v = reinterpret_cast<const uint4*>(mask)[tid];
        bool isF = (v.x == 0x3F800000u) | (v.y == 0x3F800000u) |
                   (v.z == 0x3F800000u) | (v.w == 0x3F800000u);
        bool isB = ((v.x > 1u) & (v.x != 0x3F800000u)) |
                   ((v.y > 1u) & (v.y != 0x3F800000u)) |
                   ((v.z > 1u) & (v.z != 0x3F800000u)) |
                   ((v.w > 1u) & (v.w != 0x3F800000u));
        unsigned bF = __ballot_sync(0xFFFFFFFFu, isF);
        unsigned bB = __ballot_sync(0xFFFFFFFFu, isB);
        if (lane == 0) {
            int f = (bF ? 1 : 0) | (bB ? 2 : 0);
            if (f) atomicOr(&sFlags, f);
        }
    }
    __syncthreads();
    int flags = sFlags;
    int kind = (flags & 1) ? 2 : ((flags & 2) ? 0 : 1);

    size_t mbase = ((size_t)b * N_ + i) * N_;

    // phase 0a: batched mask loads, then ballots
    bool vv[4];
    #pragma unroll
    for (int r = 0; r < 4; ++r) {
        int j = r * 256 + warp * 32 + lane;
        if (kind == 0)      vv[r] = ((const unsigned char*)mask)[mbase + j] != 0;
        else if (kind == 1) vv[r] = ((const int*)mask)[mbase + j] != 0;
        else                vv[r] = ((const float*)mask)[mbase + j] != 0.0f;
    }
    unsigned bal[4];
    #pragma unroll
    for (int r = 0; r < 4; ++r)
        bal[r] = __ballot_sync(0xFFFFFFFFu, vv[r]);
    if (lane == 0) {
        sWc[0 * 8 + warp] = __popc(bal[0]);
        sWc[1 * 8 + warp] = __popc(bal[1]);
        sWc[2 * 8 + warp] = __popc(bal[2]);
        sWc[3 * 8 + warp] = __popc(bal[3]);
    }
    __syncthreads();

    // phase 0b: exclusive scan over the 32 counts (warp 0)
    if (warp == 0) {
        int c = sWc[lane];
        int x = c;
        #pragma unroll
        for (int off = 1; off < 32; off <<= 1) {
            int y = __shfl_up_sync(0xFFFFFFFFu, x, off);
            if (lane >= off) x += y;
        }
        sOff[lane] = x - c;
        if (lane == 31) sCnt = x;
    }
    __syncthreads();
    int cnt = sCnt;
    int pad = (cnt + 7) & ~7;

    // phase 0c: indexed writes (sorted j order) + sentinel padding
    #pragma unroll
    for (int r = 0; r < 4; ++r) {
        if ((bal[r] >> lane) & 1u) {
            int pos = sOff[r * 8 + warp] + __popc(bal[r] & ((1u << lane) - 1u));
            sh_idx[pos] = (unsigned short)(r * 256 + warp * 32 + lane);
        }
    }
    if (tid < pad - cnt) sh_idx[cnt + tid] = 0;
    __syncthreads();

    int h   = tid >> 6;
    int l64 = tid & 63;
    int wig = (tid >> 5) & 1;

    const float* dstv = g_dst + (size_t)(b * H_ + h) * N_;
    float srci = __ldg(g_src + (size_t)(b * H_ + h) * N_ + i);

    // phase 1: e -> p -> packed (p-hi-bits | j), sum quantized p
    float lsum = 0.f;
    for (int k = l64; k < pad; k += 64) {
        unsigned j = sh_idx[k];
        unsigned pb = 0;
        if (k < cnt) {
            float x = srci + dstv[j];
            float e = x > 0.f ? x : 0.2f * x;
            float p = __expf(e);
            pb = (__float_as_uint(p) & ~1023u) | j;
        }
        sh_pk[h][k] = pb;
        lsum += __uint_as_float(pb & ~1023u);
    }
    #pragma unroll
    for (int off = 16; off; off >>= 1)
        lsum += __shfl_xor_sync(0xFFFFFFFFu, lsum, off);
    if (lane == 0) sred[h][wig] = lsum;
    __syncthreads();

    // phase 2: warp = (head, k-parity over quads). Lane owns a d-pair.
    // One LDS.128 broadcasts 4 packed neighbors; 4 independent gathers.
    {
        int hh   = warp >> 1;
        int half = warp & 1;
        const float2* whb = reinterpret_cast<const float2*>(
            g_Wh + (size_t)b * N_ * O_ + hh * D_) + lane;
        const uint4* pk4 = reinterpret_cast<const uint4*>(sh_pk[hh]);
        float ax = 0.f, ay = 0.f;
        int nq = pad >> 2;                      // number of quads
        for (int q = half; q < nq; q += 2) {
            uint4 pb = pk4[q];
            float2 w0 = whb[(size_t)(pb.x & 1023u) * 128];
            float2 w1 = whb[(size_t)(pb.y & 1023u) * 128];
            float2 w2 = whb[(size_t)(pb.z & 1023u) * 128];
            float2 w3 = whb[(size_t)(pb.w & 1023u) * 128];
            float p0 = __uint_as_float(pb.x & ~1023u);
            float p1 = __uint_as_float(pb.y & ~1023u);
            float p2 = __uint_as_float(pb.z & ~1023u);
            float p3 = __uint_as_float(pb.w & ~1023u);
            ax = fmaf(p0, w0.x, ax);
            ay = fmaf(p0, w0.y, ay);
            ax = fmaf(p1, w1.x, ax);
            ay = fmaf(p1, w1.y, ay);
            ax = fmaf(p2, w2.x, ax);
            ay = fmaf(p2, w2.y, ay);
            ax = fmaf(p3, w3.x, ax);
            ay = fmaf(p3, w3.y, ay);
        }
        sacc[warp][lane * 2]     = ax;
        sacc[warp][lane * 2 + 1] = ay;
    }
    __syncthreads();

    // combine halves + scale + coalesced store
    {
        int hh = tid >> 6;
        int d  = tid & 63;
        float ssum = sred[hh][0] + sred[hh][1];
        float inv = (ssum > 0.f) ? (1.0f / ssum) : 0.f;
        float v = (sacc[2 * hh][d] + sacc[2 * hh + 1][d]) * inv;
        out[(size_t)bid * O_ + hh * D_ + d] = v;
    }
}

// ---------------------------------------------------------------------------
extern "C" void kernel_launch(void* const* d_in, const int* in_sizes, int n_in,
                              void* d_out, int out_size) {
    const float* h = nullptr;
    const float* W = nullptr;
    const float* a = nullptr;
    const void*  mask = nullptr;

    for (int idx = 0; idx < n_in; ++idx) {
        switch (in_sizes[idx]) {
            case B_ * N_ * K_: h    = (const float*)d_in[idx]; break;
            case K_ * O_:      W    = (const float*)d_in[idx]; break;
            case H_ * 2 * D_:  a    = (const float*)d_in[idx]; break;
            case B_ * N_ * N_: mask = d_in[idx];               break;
        }
    }
    if (!h)    h    = (const float*)d_in[0];
    if (!W)    W    = (const float*)d_in[1];
    if (!a)    a    = (const float*)d_in[2];
    if (!mask) mask = d_in[3];

    gemm_kernel<<<dim3((B_ * N_) / 128, H_), 256>>>(h, W, a);
    attn_kernel<<<B_ * N_, 256>>>(mask, (float*)d_out);
}